// round 2
// baseline (speedup 1.0000x reference)
#include <cuda_runtime.h>

// Problem constants (fixed by the dataset)
constexpr int B = 256;     // batch
constexpr int H = 1024;    // hidden
constexpr int L = 10000;   // labels
constexpr int D = 8;       // expert hidden
constexpr int KC = 32;     // K-chunk staged in smem
constexpr int LPB = 8;     // labels per CTA

// CTA: 256 threads = 8 warps. Warp w owns label (blockIdx.x*8 + w).
// Thread (w, lane) owns batch rows lane*8 .. lane*8+7 for that label.
// Inner loop per k: 2x LDS.128 (A), 2x LDS.128 (W, warp-broadcast), 64 FFMA.
__global__ __launch_bounds__(256, 2)
void imec_mlp_kernel(const float* __restrict__ emb,
                     const float* __restrict__ W1,
                     const float* __restrict__ b1,
                     const float* __restrict__ W2,
                     const float* __restrict__ b2,
                     float* __restrict__ out)
{
    __shared__ float sA[KC][B];          // 32 KB : A transposed, sA[k][b]
    __shared__ float sW[LPB][KC * D];    //  8 KB : sW[l_loc][k*8 + d]

    const int tid   = threadIdx.x;
    const int l_loc = tid >> 5;          // 0..7  (warp id = local label)
    const int bg    = tid & 31;          // 0..31 (batch group: rows bg*8..bg*8+7)
    const int l     = blockIdx.x * LPB + l_loc;

    float acc[8][8];
#pragma unroll
    for (int i = 0; i < 8; ++i)
#pragma unroll
        for (int d = 0; d < 8; ++d) acc[i][d] = 0.0f;

    const float* embRow = emb + (size_t)tid * H;          // thread tid loads batch row tid
    const float* wRow   = W1 + (size_t)l * (H * D);       // this warp's label slab

    for (int k0 = 0; k0 < H; k0 += KC) {
        // ---- stage global -> registers (overlaps with previous compute) ----
        float4 av[KC / 4];
#pragma unroll
        for (int j = 0; j < KC / 4; ++j)
            av[j] = *reinterpret_cast<const float4*>(embRow + k0 + j * 4);

        const float4* wsrc = reinterpret_cast<const float4*>(wRow + (size_t)k0 * D);
        float4 wv0 = wsrc[bg * 2];       // warp covers 256 contiguous floats: coalesced
        float4 wv1 = wsrc[bg * 2 + 1];

        __syncthreads();  // previous iteration's compute must finish before overwrite

        // ---- registers -> smem (A transposed; W direct) ----
#pragma unroll
        for (int j = 0; j < KC / 4; ++j) {
            sA[j * 4 + 0][tid] = av[j].x;
            sA[j * 4 + 1][tid] = av[j].y;
            sA[j * 4 + 2][tid] = av[j].z;
            sA[j * 4 + 3][tid] = av[j].w;
        }
        reinterpret_cast<float4*>(sW[l_loc])[bg * 2]     = wv0;
        reinterpret_cast<float4*>(sW[l_loc])[bg * 2 + 1] = wv1;

        __syncthreads();

        // ---- compute: 32 k-steps, 64 FFMA each ----
#pragma unroll 4
        for (int k = 0; k < KC; ++k) {
            float a[8], w[8];
            float4 t0 = *reinterpret_cast<const float4*>(&sA[k][bg * 8]);
            float4 t1 = *reinterpret_cast<const float4*>(&sA[k][bg * 8 + 4]);
            a[0] = t0.x; a[1] = t0.y; a[2] = t0.z; a[3] = t0.w;
            a[4] = t1.x; a[5] = t1.y; a[6] = t1.z; a[7] = t1.w;
            float4 u0 = *reinterpret_cast<const float4*>(&sW[l_loc][k * 8]);
            float4 u1 = *reinterpret_cast<const float4*>(&sW[l_loc][k * 8 + 4]);
            w[0] = u0.x; w[1] = u0.y; w[2] = u0.z; w[3] = u0.w;
            w[4] = u1.x; w[5] = u1.y; w[6] = u1.z; w[7] = u1.w;
#pragma unroll
            for (int i = 0; i < 8; ++i)
#pragma unroll
                for (int d = 0; d < 8; ++d)
                    acc[i][d] = fmaf(a[i], w[d], acc[i][d]);
        }
    }

    // ---- epilogue: relu(h + b1) . W2 + b2 ----
    float4 c0 = *reinterpret_cast<const float4*>(b1 + (size_t)l * D);
    float4 c1 = *reinterpret_cast<const float4*>(b1 + (size_t)l * D + 4);
    float4 v0 = *reinterpret_cast<const float4*>(W2 + (size_t)l * D);
    float4 v1 = *reinterpret_cast<const float4*>(W2 + (size_t)l * D + 4);
    const float bias2 = b2[l];

    float bb[8] = {c0.x, c0.y, c0.z, c0.w, c1.x, c1.y, c1.z, c1.w};
    float ww[8] = {v0.x, v0.y, v0.z, v0.w, v1.x, v1.y, v1.z, v1.w};

#pragma unroll
    for (int i = 0; i < 8; ++i) {
        float s = bias2;
#pragma unroll
        for (int d = 0; d < 8; ++d)
            s += fmaxf(acc[i][d] + bb[d], 0.0f) * ww[d];
        out[(size_t)(bg * 8 + i) * L + l] = s;
    }
}

extern "C" void kernel_launch(void* const* d_in, const int* in_sizes, int n_in,
                              void* d_out, int out_size)
{
    const float* emb = (const float*)d_in[0];  // [B, H]
    const float* W1  = (const float*)d_in[1];  // [L, H, D]
    const float* b1  = (const float*)d_in[2];  // [L, D]
    const float* W2  = (const float*)d_in[3];  // [L, D]
    const float* b2  = (const float*)d_in[4];  // [L]
    float* out       = (float*)d_out;          // [B, L]

    imec_mlp_kernel<<<L / LPB, 256>>>(emb, W1, b1, W2, b2, out);
}

// round 4
// speedup vs baseline: 2.5795x; 2.5795x over previous
#include <cuda_runtime.h>
#include <cstdint>

// Problem constants
constexpr int BB = 256;     // batch
constexpr int H  = 1024;    // hidden
constexpr int L  = 10000;   // labels
constexpr int MT = 128;     // M per CTA
constexpr int LPB = 16;     // labels per CTA (N = 128)
constexpr int KC = 64;      // K per chunk (bf16 => 128B rows)
constexpr int NCHUNK = H / KC;  // 16

// smem buffer layout (per buffer)
constexpr int OFF_AH = 0;
constexpr int OFF_AL = 16384;
constexpr int OFF_BH = 32768;
constexpr int OFF_BL = 49152;
constexpr int BUF_BYTES = 65536;
constexpr int SMEM_DYN = 1024 + 2 * BUF_BYTES;   // align slack + double buffer

// pre-converted embeddings: packed bf16x2 (hi parts and residual lo parts)
__device__ __align__(16) uint32_t g_embH[BB * H / 2];
__device__ __align__(16) uint32_t g_embL[BB * H / 2];

// ---------------- helpers ----------------
__device__ __forceinline__ uint32_t smem_u32(const void* p) {
    uint32_t a;
    asm("{ .reg .u64 t; cvta.to.shared.u64 t, %1; cvt.u32.u64 %0, t; }" : "=r"(a) : "l"(p));
    return a;
}
// low half = bf16(x0), high half = bf16(x1)
__device__ __forceinline__ uint32_t pack2(float x0, float x1) {
    uint32_t r;
    asm("cvt.rn.bf16x2.f32 %0, %1, %2;" : "=r"(r) : "f"(x1), "f"(x0));
    return r;
}
__device__ __forceinline__ void split2(float x0, float x1, uint32_t& h, uint32_t& l) {
    h = pack2(x0, x1);
    float h0 = __uint_as_float(h << 16);
    float h1 = __uint_as_float(h & 0xffff0000u);
    l = pack2(x0 - h0, x1 - h1);
}
__device__ __forceinline__ void ldsm4(uint32_t* r, uint32_t addr) {
    asm volatile("ldmatrix.sync.aligned.m8n8.x4.shared.b16 {%0,%1,%2,%3}, [%4];"
                 : "=r"(r[0]), "=r"(r[1]), "=r"(r[2]), "=r"(r[3]) : "r"(addr));
}
__device__ __forceinline__ void mma16816(float* c, const uint32_t* a, const uint32_t* b) {
    asm volatile(
        "mma.sync.aligned.m16n8k16.row.col.f32.bf16.bf16.f32 "
        "{%0,%1,%2,%3}, {%4,%5,%6,%7}, {%8,%9}, {%0,%1,%2,%3};"
        : "+f"(c[0]), "+f"(c[1]), "+f"(c[2]), "+f"(c[3])
        : "r"(a[0]), "r"(a[1]), "r"(a[2]), "r"(a[3]), "r"(b[0]), "r"(b[1]));
}

// ---------------- pre-kernel: emb fp32 -> bf16 hi/lo ----------------
__global__ void cvt_emb_kernel(const float* __restrict__ emb) {
    int i = blockIdx.x * blockDim.x + threadIdx.x;   // 65536 float4s
    float4 v = reinterpret_cast<const float4*>(emb)[i];
    uint32_t h01, l01, h23, l23;
    split2(v.x, v.y, h01, l01);
    split2(v.z, v.w, h23, l23);
    reinterpret_cast<uint2*>(g_embH)[i] = make_uint2(h01, h23);
    reinterpret_cast<uint2*>(g_embL)[i] = make_uint2(l01, l23);
}

// ---------------- main kernel ----------------
__global__ __launch_bounds__(256, 1)
void imec_mma_kernel(const float* __restrict__ W1,
                     const float* __restrict__ b1,
                     const float* __restrict__ W2,
                     const float* __restrict__ b2,
                     float* __restrict__ out)
{
    extern __shared__ char smraw[];
    uint32_t sraw = smem_u32(smraw);
    uint32_t sb = (sraw + 1023u) & ~1023u;
    char* smc = smraw + (sb - sraw);

    const int tid  = threadIdx.x;
    const int lane = tid & 31;
    const int wid  = tid >> 5;
    const int wm   = wid & 3;      // warp M row (32 rows each)
    const int wn   = wid >> 2;     // warp N col (64 cols each)

    const int lg = blockIdx.x >> 1;
    const int mt = blockIdx.x & 1;
    const int m0 = mt * MT;
    const int l0 = lg * LPB;

    // ---- staging thread mapping ----
    const int ar = tid >> 1;          // A row 0..127
    const int ah = tid & 1;           // A k-half (32 k each)
    const int lt = tid >> 4;          // B: label 0..15
    const int sq = tid & 15;          // B: 4-h slice 0..15

    // ---- ldmatrix per-lane invariants ----
    // A: rows = wm*32 + mi*16 + (lane&15); lanes 16-31 take k+8
    uint32_t aRow[2], aXor[2];
#pragma unroll
    for (int mi = 0; mi < 2; ++mi) {
        int r = wm * 32 + mi * 16 + (lane & 15);
        aRow[mi] = (uint32_t)r * 128u;
        aXor[mi] = (uint32_t)(r & 7) << 4;
    }
    const uint32_t aKadd = (uint32_t)(lane >> 4) << 4;   // 0 or 16 bytes

    // B: rows(n) = wn*64 + nb*16 + ((lane>>4)<<3) + (lane&7); k+8 from bit3
    uint32_t bRow[4], bXor[4];
#pragma unroll
    for (int nb = 0; nb < 4; ++nb) {
        int r = wn * 64 + nb * 16 + ((lane >> 4) << 3) + (lane & 7);
        bRow[nb] = (uint32_t)r * 128u;
        bXor[nb] = (uint32_t)(r & 7) << 4;
    }
    const uint32_t bKadd = (uint32_t)((lane >> 3) & 1) << 4;

    float acc[2][8][4];
#pragma unroll
    for (int mi = 0; mi < 2; ++mi)
#pragma unroll
        for (int ni = 0; ni < 8; ++ni)
#pragma unroll
            for (int k = 0; k < 4; ++k) acc[mi][ni][k] = 0.0f;

    // prefetch registers
    uint4 avh[4], avl[4];
    float4 bv[8];

    auto ldg_stage = [&](int c) {
        const uint4* srcH = reinterpret_cast<const uint4*>(
            g_embH + (size_t)(m0 + ar) * 512 + c * 32 + ah * 16);
        const uint4* srcL = reinterpret_cast<const uint4*>(
            g_embL + (size_t)(m0 + ar) * 512 + c * 32 + ah * 16);
#pragma unroll
        for (int j = 0; j < 4; ++j) { avh[j] = srcH[j]; avl[j] = srcL[j]; }
        const float4* bsrc = reinterpret_cast<const float4*>(
            W1 + (size_t)(l0 + lt) * (H * 8) + ((size_t)c * KC + sq * 4) * 8);
#pragma unroll
        for (int j = 0; j < 8; ++j) bv[j] = bsrc[j];
    };

    auto sts_stage = [&](int p) {
        char* buf = smc + p * BUF_BYTES;
        const uint32_t axorl = (uint32_t)(ar & 7) << 4;
#pragma unroll
        for (int j = 0; j < 4; ++j) {
            uint32_t off = (uint32_t)ar * 128u + (((uint32_t)(ah * 64 + j * 16)) ^ axorl);
            *reinterpret_cast<uint4*>(buf + OFF_AH + off) = avh[j];
            *reinterpret_cast<uint4*>(buf + OFF_AL + off) = avl[j];
        }
        const float* fp = reinterpret_cast<const float*>(bv);   // fp[h*8+d], h=0..3
#pragma unroll
        for (int d = 0; d < 8; ++d) {
            uint32_t h01, l01, h23, l23;
            split2(fp[0 + d], fp[8 + d],  h01, l01);
            split2(fp[16 + d], fp[24 + d], h23, l23);
            int n = lt * 8 + d;
            uint32_t off = (uint32_t)n * 128u + (((uint32_t)(sq * 8)) ^ ((uint32_t)(n & 7) << 4));
            *reinterpret_cast<uint2*>(buf + OFF_BH + off) = make_uint2(h01, h23);
            *reinterpret_cast<uint2*>(buf + OFF_BL + off) = make_uint2(l01, l23);
        }
    };

    auto compute = [&](int p) {
        const uint32_t base = sb + (uint32_t)p * BUF_BYTES;
        const uint32_t bAH = base + OFF_AH, bAL = base + OFF_AL;
        const uint32_t bBH = base + OFF_BH, bBL = base + OFF_BL;
#pragma unroll
        for (int ks = 0; ks < 4; ++ks) {
            const uint32_t koff = (uint32_t)ks * 32u;
            uint32_t a_h[2][4], a_l[2][4], b_h[4][4], b_l[4][4];
#pragma unroll
            for (int mi = 0; mi < 2; ++mi)
                ldsm4(a_h[mi], bAH + aRow[mi] + ((koff + aKadd) ^ aXor[mi]));
#pragma unroll
            for (int nb = 0; nb < 4; ++nb)
                ldsm4(b_h[nb], bBH + bRow[nb] + ((koff + bKadd) ^ bXor[nb]));
#pragma unroll
            for (int mi = 0; mi < 2; ++mi)
#pragma unroll
                for (int ni = 0; ni < 8; ++ni)
                    mma16816(acc[mi][ni], a_h[mi], &b_h[ni >> 1][(ni & 1) * 2]);
#pragma unroll
            for (int nb = 0; nb < 4; ++nb)
                ldsm4(b_l[nb], bBL + bRow[nb] + ((koff + bKadd) ^ bXor[nb]));
#pragma unroll
            for (int mi = 0; mi < 2; ++mi)
#pragma unroll
                for (int ni = 0; ni < 8; ++ni)
                    mma16816(acc[mi][ni], a_h[mi], &b_l[ni >> 1][(ni & 1) * 2]);
#pragma unroll
            for (int mi = 0; mi < 2; ++mi)
                ldsm4(a_l[mi], bAL + aRow[mi] + ((koff + aKadd) ^ aXor[mi]));
#pragma unroll
            for (int mi = 0; mi < 2; ++mi)
#pragma unroll
                for (int ni = 0; ni < 8; ++ni)
                    mma16816(acc[mi][ni], a_l[mi], &b_h[ni >> 1][(ni & 1) * 2]);
        }
    };

    // ---- software pipeline ----
    ldg_stage(0);
    sts_stage(0);
    __syncthreads();
    for (int c = 0; c < NCHUNK; ++c) {
        const int p = c & 1;
        if (c + 1 < NCHUNK) ldg_stage(c + 1);
        compute(p);
        if (c + 1 < NCHUNK) sts_stage(p ^ 1);
        __syncthreads();
    }

    // ---- epilogue: relu(h + b1) . W2 + b2, quad-reduce over d ----
    const int gid = lane >> 2;
    const int tq  = lane & 3;
#pragma unroll
    for (int ni = 0; ni < 8; ++ni) {
        const int l = l0 + wn * 8 + ni;
        float2 bbv = *reinterpret_cast<const float2*>(b1 + (size_t)l * 8 + tq * 2);
        float2 wwv = *reinterpret_cast<const float2*>(W2 + (size_t)l * 8 + tq * 2);
        const float b2v = __ldg(b2 + l);
#pragma unroll
        for (int mi = 0; mi < 2; ++mi) {
            float s0 = fmaxf(acc[mi][ni][0] + bbv.x, 0.0f) * wwv.x
                     + fmaxf(acc[mi][ni][1] + bbv.y, 0.0f) * wwv.y;
            float s1 = fmaxf(acc[mi][ni][2] + bbv.x, 0.0f) * wwv.x
                     + fmaxf(acc[mi][ni][3] + bbv.y, 0.0f) * wwv.y;
            s0 += __shfl_xor_sync(0xffffffffu, s0, 1);
            s0 += __shfl_xor_sync(0xffffffffu, s0, 2);
            s1 += __shfl_xor_sync(0xffffffffu, s1, 1);
            s1 += __shfl_xor_sync(0xffffffffu, s1, 2);
            if (tq == 0) {
                const int b = m0 + wm * 32 + mi * 16 + gid;
                out[(size_t)b * L + l]       = s0 + b2v;
                out[(size_t)(b + 8) * L + l] = s1 + b2v;
            }
        }
    }
}

extern "C" void kernel_launch(void* const* d_in, const int* in_sizes, int n_in,
                              void* d_out, int out_size)
{
    const float* emb = (const float*)d_in[0];  // [B, H]
    const float* W1  = (const float*)d_in[1];  // [L, H, 8]
    const float* b1  = (const float*)d_in[2];  // [L, 8]
    const float* W2  = (const float*)d_in[3];  // [L, 8]
    const float* b2  = (const float*)d_in[4];  // [L]
    float* out       = (float*)d_out;          // [B, L]

    cudaFuncSetAttribute(imec_mma_kernel,
                         cudaFuncAttributeMaxDynamicSharedMemorySize, SMEM_DYN);

    cvt_emb_kernel<<<BB * H / 4 / 256, 256>>>(emb);
    imec_mma_kernel<<<(L / LPB) * 2, 256, SMEM_DYN>>>(W1, b1, W2, b2, out);
}